// round 17
// baseline (speedup 1.0000x reference)
#include <cuda_runtime.h>
#include <cuda_fp16.h>
#include <math.h>
#include <stdint.h>

// ---------------------------------------------------------------------------
// Problem constants
// ---------------------------------------------------------------------------
constexpr int B    = 4;
constexpr int N    = 2048;
constexpr int D    = 1024;
constexpr int E    = 24;
constexpr int H    = 8;
constexpr int HD   = 128;
constexpr int BN_TOK = B * N;          // 8192 tokens
constexpr int NSLOT  = BN_TOK * H;     // 65536 (token,slot) pairs

// Grouped-GEMM tiling
constexpr int TQ = 128;                // rows per expert tile
constexpr int NT_MAX = NSLOT / TQ + E; // 536 max tiles

// ---------------------------------------------------------------------------
// Scratch (device globals — no allocations allowed)
// ---------------------------------------------------------------------------
__device__ __half2 g_kh2[(HD / 2) * BN_TOK];   // 2 MB  K hi,  pair-major [hd-pair][token]
__device__ __half2 g_kl2[(HD / 2) * BN_TOK];   // 2 MB  K lo*2^10
__device__ __half2 g_vh2[HD * (BN_TOK / 2)];   // 2 MB  V f16 transposed [hd][token-pair]
__device__ __half2 g_qh2[NSLOT * (HD / 2)];    // 16 MB Q hi (pre-scaled) [slot][pair]
__device__ __half2 g_ql2[NSLOT * (HD / 2)];    // 16 MB Q lo*2^10
__device__ __half2 g_attno2[NSLOT * (HD / 2)]; // 16 MB attn out f16 [slot][hd-pair]
__device__ __half2 g_ws2[(size_t)NSLOT * (D / 2)]; // 134 MB combine scratch f16 [slot][pair]
// pre-split inputs (convert-once)
__device__ __half2 g_xh2[BN_TOK * (D / 2)];    // 16 MB x hi [token][pair]
__device__ __half2 g_xl2[BN_TOK * (D / 2)];    // 16 MB x lo*2^10
__device__ __half2 g_wqh2[(size_t)E * (D / 2) * HD];  // 6.3 MB Wq hi [e][kpair][n]
__device__ __half2 g_wql2[(size_t)E * (D / 2) * HD];  // 6.3 MB Wq lo*2^10
__device__ __half2 g_woh2[(size_t)E * (HD / 2) * D];  // 6.3 MB Wo f16 [e][kpair][n]
__device__ __half2 g_wkvh2[(D / 2) * (2 * HD)];       // 0.5 MB Wkv hi [kpair][n]
__device__ __half2 g_wkvl2[(D / 2) * (2 * HD)];       // 0.5 MB Wkv lo*2^10
__device__ int   g_topi[NSLOT];
__device__ float g_gates[NSLOT];
__device__ float g_aux[2 * E + 1];
// expert bucketing
__device__ int g_ecnt[E];
__device__ int g_eoff[E + 1];
__device__ int g_ecursor[E];
__device__ int g_slots[NSLOT];
__device__ int g_tile_e[NT_MAX];
__device__ int g_tile_r0[NT_MAX];
__device__ int g_ntiles;

// ---------------------------------------------------------------------------
// helpers
// ---------------------------------------------------------------------------
__device__ __forceinline__ void mma_f16(float* d, const uint32_t* a, const uint32_t* b) {
    asm volatile(
        "mma.sync.aligned.m16n8k16.row.col.f32.f16.f16.f32 "
        "{%0,%1,%2,%3}, {%4,%5,%6,%7}, {%8,%9}, {%0,%1,%2,%3};\n"
        : "+f"(d[0]), "+f"(d[1]), "+f"(d[2]), "+f"(d[3])
        : "r"(a[0]), "r"(a[1]), "r"(a[2]), "r"(a[3]), "r"(b[0]), "r"(b[1]));
}
__device__ __forceinline__ void h2split(float x, float y, __half2& hi, __half2& lo) {
    hi = __floats2half2_rn(x, y);
    float2 hf = __half22float2(hi);
    lo = __floats2half2_rn((x - hf.x) * 1024.f, (y - hf.y) * 1024.f);
}
constexpr float LO_INV = 1.f / 1024.f;
constexpr float QSC = 0.08838834764831845f * 1.44269504088896340736f; // scale*log2e

__device__ __forceinline__ void cp16(void* smem, const void* gmem) {
    uint32_t s = (uint32_t)__cvta_generic_to_shared(smem);
    asm volatile("cp.async.cg.shared.global [%0], [%1], 16;\n" :: "r"(s), "l"(gmem));
}
__device__ __forceinline__ void cp_commit() {
    asm volatile("cp.async.commit_group;\n");
}
__device__ __forceinline__ void cp_wait0() {
    asm volatile("cp.async.wait_group 0;\n" ::: "memory");
}

// ---------------------------------------------------------------------------
// Kernel 0: zero aux + expert histogram
// ---------------------------------------------------------------------------
__global__ void init_aux_kernel() {
    int tid = threadIdx.x;
    if (tid < 2 * E + 1) g_aux[tid] = 0.f;
    if (tid < E) g_ecnt[tid] = 0;
}

// ---------------------------------------------------------------------------
// Pre-split kernels (convert-once)
// ---------------------------------------------------------------------------
__global__ __launch_bounds__(256) void xsplit_kernel(const float* __restrict__ x) {
    int t = blockIdx.x;
    int c = threadIdx.x * 4;
    float4 v = *reinterpret_cast<const float4*>(x + (size_t)t * D + c);
    __half2 h0, l0, h1, l1;
    h2split(v.x, v.y, h0, l0);
    h2split(v.z, v.w, h1, l1);
    int p = c >> 1;
    g_xh2[(size_t)t * (D / 2) + p]     = h0;
    g_xh2[(size_t)t * (D / 2) + p + 1] = h1;
    g_xl2[(size_t)t * (D / 2) + p]     = l0;
    g_xl2[(size_t)t * (D / 2) + p + 1] = l1;
}

__global__ __launch_bounds__(128) void wqsplit_kernel(const float* __restrict__ Wq) {
    int p = blockIdx.x;      // kpair 0..511
    int e = blockIdx.y;
    int n = threadIdx.x;     // 0..127
    const float* w = Wq + (size_t)e * D * HD;
    float a = w[(size_t)(2 * p) * HD + n];
    float b2 = w[(size_t)(2 * p + 1) * HD + n];
    __half2 hh, ll;
    h2split(a, b2, hh, ll);
    size_t o = ((size_t)e * (D / 2) + p) * HD + n;
    g_wqh2[o] = hh;
    g_wql2[o] = ll;
}

__global__ __launch_bounds__(256) void wosplit_kernel(const float* __restrict__ Wo) {
    int p = blockIdx.x;      // kpair 0..63
    int e = blockIdx.y;
    const float* w = Wo + (size_t)e * HD * D;
    for (int n = threadIdx.x; n < D; n += 256) {
        g_woh2[((size_t)e * (HD / 2) + p) * D + n] =
            __floats2half2_rn(w[(size_t)(2 * p) * D + n], w[(size_t)(2 * p + 1) * D + n]);
    }
}

__global__ __launch_bounds__(256) void wkvsplit_kernel(const float* __restrict__ Wkv) {
    int p = blockIdx.x;      // kpair 0..511
    int n = threadIdx.x;     // 0..255
    float a = Wkv[(size_t)(2 * p) * (2 * HD) + n];
    float b2 = Wkv[(size_t)(2 * p + 1) * (2 * HD) + n];
    __half2 hh, ll;
    h2split(a, b2, hh, ll);
    g_wkvh2[(size_t)p * (2 * HD) + n] = hh;
    g_wkvl2[(size_t)p * (2 * HD) + n] = ll;
}

// ---------------------------------------------------------------------------
// Kernel 1: gating — Wg[task] cached in smem
// ---------------------------------------------------------------------------
__global__ __launch_bounds__(256) void gating_kernel(
    const float* __restrict__ x, const int* __restrict__ task_bh,
    const float* __restrict__ Wg)
{
    extern __shared__ float s_wg[];            // D * E floats = 96 KB
    __shared__ float s_aux[2 * E + 1];
    __shared__ int   s_ecnt[E];
    int tid = threadIdx.x;
    if (tid < 2 * E + 1) s_aux[tid] = 0.f;
    if (tid < E) s_ecnt[tid] = 0;

    int warp = tid >> 5, lane = tid & 31;
    int t = blockIdx.x * 8 + warp;
    int b = t >> 11;
    int task = task_bh[b];
    const float* wg = Wg + (size_t)task * D * E;

    for (int idx = tid; idx < D * E / 4; idx += 256) {
        reinterpret_cast<float4*>(s_wg)[idx] =
            reinterpret_cast<const float4*>(wg)[idx];
    }
    __syncthreads();

    const float* xrow = x + (size_t)t * D;

    float acc[E];
#pragma unroll
    for (int e = 0; e < E; e++) acc[e] = 0.f;

    for (int i = lane; i < D; i += 32) {
        float xv = xrow[i];
        const float4* w4 = reinterpret_cast<const float4*>(s_wg + (size_t)i * E);
#pragma unroll
        for (int j = 0; j < 6; j++) {
            float4 v = w4[j];
            acc[4*j+0] += xv * v.x; acc[4*j+1] += xv * v.y;
            acc[4*j+2] += xv * v.z; acc[4*j+3] += xv * v.w;
        }
    }
#pragma unroll
    for (int e = 0; e < E; e++) {
#pragma unroll
        for (int off = 16; off >= 1; off >>= 1)
            acc[e] += __shfl_xor_sync(0xffffffffu, acc[e], off);
    }
    float mx = acc[0];
#pragma unroll
    for (int e = 1; e < E; e++) mx = fmaxf(mx, acc[e]);
    float p[E]; float s = 0.f;
#pragma unroll
    for (int e = 0; e < E; e++) { p[e] = __expf(acc[e] - mx); s += p[e]; }
    float inv_s = 1.f / s;
    float lse = mx + __logf(s);

    if (lane < E) atomicAdd(&s_aux[E + lane], p[lane] * inv_s);
    if (lane == 0) {
        atomicAdd(&s_aux[2 * E], lse * lse);
        float tv[H]; int ti[H]; float gsum = 0.f;
#pragma unroll
        for (int h = 0; h < H; h++) {
            float best = -1.f; int bi = 0;
#pragma unroll
            for (int e = 0; e < E; e++)
                if (p[e] > best) { best = p[e]; bi = e; }
            tv[h] = best * inv_s; ti[h] = bi; p[bi] = -2.f;
            gsum += tv[h];
            atomicAdd(&s_aux[bi], 1.0f);
            atomicAdd(&s_ecnt[bi], 1);
        }
        float ig = 1.f / gsum;
#pragma unroll
        for (int h = 0; h < H; h++) {
            g_topi[t * H + h]  = ti[h];
            g_gates[t * H + h] = tv[h] * ig;
        }
    }
    __syncthreads();
    if (tid < 2 * E + 1) atomicAdd(&g_aux[tid], s_aux[tid]);
    if (tid < E) atomicAdd(&g_ecnt[tid], s_ecnt[tid]);
}

// ---------------------------------------------------------------------------
// Kernel 2: serial scan over experts → offsets + tile table
// ---------------------------------------------------------------------------
__global__ void scan_kernel() {
    if (threadIdx.x == 0) {
        int off = 0, nt = 0;
        for (int e = 0; e < E; e++) {
            g_eoff[e] = off;
            g_ecursor[e] = 0;
            int c = g_ecnt[e];
            for (int r = 0; r < c; r += TQ) {
                g_tile_e[nt]  = e;
                g_tile_r0[nt] = off + r;
                nt++;
            }
            off += c;
        }
        g_eoff[E] = off;
        g_ntiles = nt;
    }
}

// ---------------------------------------------------------------------------
// Kernel 3: scatter slot ids into expert buckets
// ---------------------------------------------------------------------------
__global__ void scatter_kernel() {
    int i = blockIdx.x * 256 + threadIdx.x;
    int e = g_topi[i];
    int pos = atomicAdd(&g_ecursor[e], 1);
    g_slots[g_eoff[e] + pos] = i;
}

// ---------------------------------------------------------------------------
// Shared tiling constants for f16-compensated GEMM pipelines
// ---------------------------------------------------------------------------
constexpr int QG_K  = 64;    // floats per k-chunk (32 pairs)
constexpr int QA_STR = 36;   // Ahi/Alo [row 128][kpair 32 + pad]  (half2)
constexpr int QB_STR = 136;  // Bhi/Blo [kpair 32][n 128 + pad]    (half2)
constexpr int QABUF = TQ * QA_STR;   // 4608
constexpr int QBBUF = 32 * QB_STR;   // 4352
constexpr int QNCH  = D / QG_K;      // 16 chunks

// ---------------------------------------------------------------------------
// Kernel 4: kv = x @ Wkv + bkv — f16-compensated tensor GEMM.
// grid (64, 2): y=0 → K cols (hi/lo pair-major), y=1 → V cols (f16 transposed)
// ---------------------------------------------------------------------------
__global__ __launch_bounds__(512, 1) void kvmma_kernel(const float* __restrict__ bkv)
{
    extern __shared__ __half2 qsm[];
    __half2* Ahi = qsm;
    __half2* Alo = Ahi + 2 * QABUF;
    __half2* Bhi = Alo + 2 * QABUF;
    __half2* Blo = Bhi + 2 * QBBUF;

    int tid = threadIdx.x;
    int t0 = blockIdx.x * TQ;          // token base
    int colbase = blockIdx.y * 128;    // 0 = K, 128 = V

    int warp = tid >> 5, lane = tid & 31;
    int g = lane >> 2, tg = lane & 3;
    int rg = warp & 7, ch = warp >> 3;
    int r_a = rg * 16 + g, r_b = r_a + 8;

    {
        for (int idx = tid; idx < TQ * 8; idx += 512) {
            int r = idx >> 3, pq = (idx & 7) * 4;
            size_t src = (size_t)(t0 + r) * (D / 2) + pq;
            cp16(Ahi + r * QA_STR + pq, g_xh2 + src);
            cp16(Alo + r * QA_STR + pq, g_xl2 + src);
        }
        for (int idx = tid; idx < 32 * 32; idx += 512) {
            int p = idx >> 5, nq = (idx & 31) * 4;
            size_t src = (size_t)p * (2 * HD) + colbase + nq;
            cp16(Bhi + p * QB_STR + nq, g_wkvh2 + src);
            cp16(Blo + p * QB_STR + nq, g_wkvl2 + src);
        }
        cp_commit();
    }

    float scc[8][4] = {};
    float scl[8][4] = {};

    for (int it = 0; it < QNCH; it++) {
        int buf = it & 1;
        cp_wait0();
        __syncthreads();

        if (it + 1 < QNCH) {
            int kp0 = (it + 1) * (QG_K / 2);
            int bn = buf ^ 1;
            __half2* AhiN = Ahi + bn * QABUF;
            __half2* AloN = Alo + bn * QABUF;
            __half2* BhiN = Bhi + bn * QBBUF;
            __half2* BloN = Blo + bn * QBBUF;
            for (int idx = tid; idx < TQ * 8; idx += 512) {
                int r = idx >> 3, pq = (idx & 7) * 4;
                size_t src = (size_t)(t0 + r) * (D / 2) + kp0 + pq;
                cp16(AhiN + r * QA_STR + pq, g_xh2 + src);
                cp16(AloN + r * QA_STR + pq, g_xl2 + src);
            }
            for (int idx = tid; idx < 32 * 32; idx += 512) {
                int p = idx >> 5, nq = (idx & 31) * 4;
                size_t src = (size_t)(kp0 + p) * (2 * HD) + colbase + nq;
                cp16(BhiN + p * QB_STR + nq, g_wkvh2 + src);
                cp16(BloN + p * QB_STR + nq, g_wkvl2 + src);
            }
            cp_commit();
        }

        __half2* AhiB = Ahi + buf * QABUF;
        __half2* AloB = Alo + buf * QABUF;
        __half2* BhiB = Bhi + buf * QBBUF;
        __half2* BloB = Blo + buf * QBBUF;

#pragma unroll
        for (int ks = 0; ks < 4; ks++) {
            const __half2* ah0 = AhiB + r_a * QA_STR + 8 * ks + tg;
            const __half2* ah1 = AhiB + r_b * QA_STR + 8 * ks + tg;
            const __half2* al0 = AloB + r_a * QA_STR + 8 * ks + tg;
            const __half2* al1 = AloB + r_b * QA_STR + 8 * ks + tg;
            uint32_t ah[4] = { *reinterpret_cast<const uint32_t*>(ah0),
                               *reinterpret_cast<const uint32_t*>(ah1),
                               *reinterpret_cast<const uint32_t*>(ah0 + 4),
                               *reinterpret_cast<const uint32_t*>(ah1 + 4) };
            uint32_t al[4] = { *reinterpret_cast<const uint32_t*>(al0),
                               *reinterpret_cast<const uint32_t*>(al1),
                               *reinterpret_cast<const uint32_t*>(al0 + 4),
                               *reinterpret_cast<const uint32_t*>(al1 + 4) };
            const __half2* bh0 = BhiB + (8 * ks + tg) * QB_STR + ch * 64 + g;
            const __half2* bh1 = BhiB + (8 * ks + 4 + tg) * QB_STR + ch * 64 + g;
            const __half2* bl0 = BloB + (8 * ks + tg) * QB_STR + ch * 64 + g;
            const __half2* bl1 = BloB + (8 * ks + 4 + tg) * QB_STR + ch * 64 + g;
#pragma unroll
            for (int nc = 0; nc < 8; nc++) {
                uint32_t bh[2] = { *reinterpret_cast<const uint32_t*>(bh0 + 8 * nc),
                                   *reinterpret_cast<const uint32_t*>(bh1 + 8 * nc) };
                uint32_t bl[2] = { *reinterpret_cast<const uint32_t*>(bl0 + 8 * nc),
                                   *reinterpret_cast<const uint32_t*>(bl1 + 8 * nc) };
                mma_f16(scc[nc], ah, bh);
                mma_f16(scl[nc], al, bh);
                mma_f16(scl[nc], ah, bl);
            }
        }
        __syncthreads();
    }

    if (colbase == 0) {
#pragma unroll
        for (int nc = 0; nc < 8; nc++) {
            int c = ch * 64 + 8 * nc + 2 * tg;
            float b0 = bkv[c], b1 = bkv[c + 1];
            float v0 = scc[nc][0] + scl[nc][0] * LO_INV + b0;
            float v1 = scc[nc][1] + scl[nc][1] * LO_INV + b1;
            float v2 = scc[nc][2] + scl[nc][2] * LO_INV + b0;
            float v3 = scc[nc][3] + scl[nc][3] * LO_INV + b1;
            int p = c >> 1;
            __half2 hh, ll;
            h2split(v0, v1, hh, ll);
            g_kh2[(size_t)p * BN_TOK + t0 + r_a] = hh;
            g_kl2[(size_t)p * BN_TOK + t0 + r_a] = ll;
            h2split(v2, v3, hh, ll);
            g_kh2[(size_t)p * BN_TOK + t0 + r_b] = hh;
            g_kl2[(size_t)p * BN_TOK + t0 + r_b] = ll;
        }
    } else {
        __half* Vs = reinterpret_cast<__half*>(qsm);   // [128][130] halves
        __syncthreads();
#pragma unroll
        for (int nc = 0; nc < 8; nc++) {
            int c = ch * 64 + 8 * nc + 2 * tg;
            float b0 = bkv[128 + c], b1 = bkv[128 + c + 1];
            float v0 = scc[nc][0] + scl[nc][0] * LO_INV + b0;
            float v1 = scc[nc][1] + scl[nc][1] * LO_INV + b1;
            float v2 = scc[nc][2] + scl[nc][2] * LO_INV + b0;
            float v3 = scc[nc][3] + scl[nc][3] * LO_INV + b1;
            Vs[r_a * 130 + c]     = __float2half_rn(v0);
            Vs[r_a * 130 + c + 1] = __float2half_rn(v1);
            Vs[r_b * 130 + c]     = __float2half_rn(v2);
            Vs[r_b * 130 + c + 1] = __float2half_rn(v3);
        }
        __syncthreads();
        int tpbase = t0 >> 1;
        for (int idx = tid; idx < HD * 64; idx += 512) {
            int tp = idx & 63, k = idx >> 6;
            __half2 val = __halves2half2(Vs[(2 * tp) * 130 + k], Vs[(2 * tp + 1) * 130 + k]);
            g_vh2[(size_t)k * (BN_TOK / 2) + tpbase + tp] = val;
        }
    }
}

// ---------------------------------------------------------------------------
// Kernel 5: grouped q GEMM — f16 error-compensated mma, cp.async pipeline;
// epilogue applies attention scale and writes pre-split Q hi/lo.
// ---------------------------------------------------------------------------
__global__ __launch_bounds__(512, 1) void qgemm_kernel()
{
    extern __shared__ __half2 qsm[];
    __half2* Ahi = qsm;
    __half2* Alo = Ahi + 2 * QABUF;
    __half2* Bhi = Alo + 2 * QABUF;
    __half2* Blo = Bhi + 2 * QBBUF;
    int* s_tok  = reinterpret_cast<int*>(Blo + 2 * QBBUF);
    int* s_slot = s_tok + TQ;

    int t = blockIdx.x;
    if (t >= g_ntiles) return;
    int e = g_tile_e[t], r0 = g_tile_r0[t];
    int rend = g_eoff[e + 1];
    int tid = threadIdx.x;

    if (tid < TQ) {
        int gr = r0 + tid;
        if (gr >= rend) gr = r0;
        int s = g_slots[gr];
        s_slot[tid] = s;
        s_tok[tid]  = s >> 3;
    }
    __syncthreads();

    int warp = tid >> 5, lane = tid & 31;
    int g = lane >> 2, tg = lane & 3;
    int rg = warp & 7, ch = warp >> 3;
    int r_a = rg * 16 + g, r_b = r_a + 8;
    const size_t wq_base = (size_t)e * (D / 2) * HD;

    {
        for (int idx = tid; idx < TQ * 8; idx += 512) {
            int r = idx >> 3, pq = (idx & 7) * 4;
            size_t src = (size_t)s_tok[r] * (D / 2) + pq;
            cp16(Ahi + r * QA_STR + pq, g_xh2 + src);
            cp16(Alo + r * QA_STR + pq, g_xl2 + src);
        }
        for (int idx = tid; idx < 32 * 32; idx += 512) {
            int p = idx >> 5, nq = (idx & 31) * 4;
            size_t src = wq_base + (size_t)p * HD + nq;
            cp16(Bhi + p * QB_STR + nq, g_wqh2 + src);
            cp16(Blo + p * QB_STR + nq, g_wql2 + src);
        }
        cp_commit();
    }

    float scc[8][4] = {};
    float scl[8][4] = {};

    for (int it = 0; it < QNCH; it++) {
        int buf = it & 1;
        cp_wait0();
        __syncthreads();

        if (it + 1 < QNCH) {
            int kp0 = (it + 1) * (QG_K / 2);
            int bn = buf ^ 1;
            __half2* AhiN = Ahi + bn * QABUF;
            __half2* AloN = Alo + bn * QABUF;
            __half2* BhiN = Bhi + bn * QBBUF;
            __half2* BloN = Blo + bn * QBBUF;
            for (int idx = tid; idx < TQ * 8; idx += 512) {
                int r = idx >> 3, pq = (idx & 7) * 4;
                size_t src = (size_t)s_tok[r] * (D / 2) + kp0 + pq;
                cp16(AhiN + r * QA_STR + pq, g_xh2 + src);
                cp16(AloN + r * QA_STR + pq, g_xl2 + src);
            }
            for (int idx = tid; idx < 32 * 32; idx += 512) {
                int p = idx >> 5, nq = (idx & 31) * 4;
                size_t src = wq_base + (size_t)(kp0 + p) * HD + nq;
                cp16(BhiN + p * QB_STR + nq, g_wqh2 + src);
                cp16(BloN + p * QB_STR + nq, g_wql2 + src);
            }
            cp_commit();
        }

        __half2* AhiB = Ahi + buf * QABUF;
        __half2* AloB = Alo + buf * QABUF;
        __half2* BhiB = Bhi + buf * QBBUF;
        __half2* BloB = Blo + buf * QBBUF;

#pragma unroll
        for (int ks = 0; ks < 4; ks++) {
            const __half2* ah0 = AhiB + r_a * QA_STR + 8 * ks + tg;
            const __half2* ah1 = AhiB + r_b * QA_STR + 8 * ks + tg;
            const __half2* al0 = AloB + r_a * QA_STR + 8 * ks + tg;
            const __half2* al1 = AloB + r_b * QA_STR + 8 * ks + tg;
            uint32_t ah[4] = { *reinterpret_cast<const uint32_t*>(ah0),
                               *reinterpret_cast<const uint32_t*>(ah1),
                               *reinterpret_cast<const uint32_t*>(ah0 + 4),
                               *reinterpret_cast<const uint32_t*>(ah1 + 4) };
            uint32_t al[4] = { *reinterpret_cast<const uint32_t*>(al0),
                               *reinterpret_cast<const uint32_t*>(al1),
                               *reinterpret_cast<const uint32_t*>(al0 + 4),
                               *reinterpret_cast<const uint32_t*>(al1 + 4) };
            const __half2* bh0 = BhiB + (8 * ks + tg) * QB_STR + ch * 64 + g;
            const __half2* bh1 = BhiB + (8 * ks + 4 + tg) * QB_STR + ch * 64 + g;
            const __half2* bl0 = BloB + (8 * ks + tg) * QB_STR + ch * 64 + g;
            const __half2* bl1 = BloB + (8 * ks + 4 + tg) * QB_STR + ch * 64 + g;
#pragma unroll
            for (int nc = 0; nc < 8; nc++) {
                uint32_t bh[2] = { *reinterpret_cast<const uint32_t*>(bh0 + 8 * nc),
                                   *reinterpret_cast<const uint32_t*>(bh1 + 8 * nc) };
                uint32_t bl[2] = { *reinterpret_cast<const uint32_t*>(bl0 + 8 * nc),
                                   *reinterpret_cast<const uint32_t*>(bl1 + 8 * nc) };
                mma_f16(scc[nc], ah, bh);
                mma_f16(scl[nc], al, bh);
                mma_f16(scl[nc], ah, bl);
            }
        }
        __syncthreads();
    }

    bool va = (r0 + r_a < rend), vb = (r0 + r_b < rend);
    size_t sa = (size_t)s_slot[r_a] * (HD / 2);
    size_t sb = (size_t)s_slot[r_b] * (HD / 2);
#pragma unroll
    for (int nc = 0; nc < 8; nc++) {
        int p = ch * 32 + 4 * nc + tg;
        float o0 = (scc[nc][0] + scl[nc][0] * LO_INV) * QSC;
        float o1 = (scc[nc][1] + scl[nc][1] * LO_INV) * QSC;
        float o2 = (scc[nc][2] + scl[nc][2] * LO_INV) * QSC;
        float o3 = (scc[nc][3] + scl[nc][3] * LO_INV) * QSC;
        __half2 hh, ll;
        if (va) {
            h2split(o0, o1, hh, ll);
            g_qh2[sa + p] = hh;
            g_ql2[sa + p] = ll;
        }
        if (vb) {
            h2split(o2, o3, hh, ll);
            g_qh2[sb + p] = hh;
            g_ql2[sb + p] = ll;
        }
    }
}

// ---------------------------------------------------------------------------
// Kernel 6: flash attention — dedicated Q smem (cp.async-loaded), Q fragments
// lifted to registers once before the mainloop (loop-invariant), cp.async
// double-buffered K/V, f16-compensated QK, log2 softmax with alpha==1 skip,
// P in registers, f16 PV, f16 attn-out.
// ---------------------------------------------------------------------------
constexpr int QT = 128;
constexpr int KT = 64;
constexpr int QH_STR  = 68;
constexpr int KH_STR  = 72;
constexpr int VT2_STR = 36;
constexpr int KBUF = 64 * KH_STR;   // 4608 half2
constexpr int VBUF = HD * VT2_STR;  // 4608 half2

__global__ __launch_bounds__(256, 1) void attn_kernel()
{
    extern __shared__ __half2 smh[];
    __half2* Qhi  = smh;                      // 128*68
    __half2* Qlo  = Qhi  + QT * QH_STR;       // 128*68
    __half2* Khi  = Qlo  + QT * QH_STR;       // 2 * KBUF
    __half2* Klo  = Khi + 2 * KBUF;           // 2 * KBUF
    __half2* VhT2 = Klo + 2 * KBUF;           // 2 * VBUF

    int tid  = threadIdx.x;
    int warp = tid >> 5, lane = tid & 31;
    int g = lane >> 2, tg = lane & 3;
    int n0 = blockIdx.x * QT;
    int h  = blockIdx.y;
    int b  = blockIdx.z;
    int bN0 = b * N;

    // Q tile + tile-0 K/V: one cp.async group
    for (int idx = tid; idx < QT * 16; idx += 256) {
        int r = idx >> 4, pq = (idx & 15) * 4;
        size_t src = ((size_t)(bN0 + n0 + r) * H + h) * (HD / 2) + pq;
        cp16(Qhi + r * QH_STR + pq, g_qh2 + src);
        cp16(Qlo + r * QH_STR + pq, g_ql2 + src);
    }
    for (int idx = tid; idx < 64 * 16; idx += 256) {
        int p = idx >> 4, mq = (idx & 15) * 4;
        cp16(Khi + p * KH_STR + mq, g_kh2 + (size_t)p * BN_TOK + bN0 + mq);
        cp16(Klo + p * KH_STR + mq, g_kl2 + (size_t)p * BN_TOK + bN0 + mq);
    }
    {
        int tp0 = bN0 >> 1;
        for (int idx = tid; idx < HD * 8; idx += 256) {
            int k = idx >> 3, tq = (idx & 7) * 4;
            cp16(VhT2 + k * VT2_STR + tq, g_vh2 + (size_t)k * (BN_TOK / 2) + tp0 + tq);
        }
    }
    cp_commit();
    cp_wait0();
    __syncthreads();   // Q + tile 0 fully resident

    const int r_a = warp * 16 + g;
    const int r_b = r_a + 8;

    // lift Q fragments into registers once (Q smem never overwritten)
    uint32_t qh[8][4], ql[8][4];
#pragma unroll
    for (int ks = 0; ks < 8; ks++) {
        qh[ks][0] = *reinterpret_cast<const uint32_t*>(Qhi + r_a * QH_STR + 8 * ks + tg);
        qh[ks][1] = *reinterpret_cast<const uint32_t*>(Qhi + r_b * QH_STR + 8 * ks + tg);
        qh[ks][2] = *reinterpret_cast<const uint32_t*>(Qhi + r_a * QH_STR + 8 * ks + tg + 4);
        qh[ks][3] = *reinterpret_cast<const uint32_t*>(Qhi + r_b * QH_STR + 8 * ks + tg + 4);
        ql[ks][0] = *reinterpret_cast<const uint32_t*>(Qlo + r_a * QH_STR + 8 * ks + tg);
        ql[ks][1] = *reinterpret_cast<const uint32_t*>(Qlo + r_b * QH_STR + 8 * ks + tg);
        ql[ks][2] = *reinterpret_cast<const uint32_t*>(Qlo + r_a * QH_STR + 8 * ks + tg + 4);
        ql[ks][3] = *reinterpret_cast<const uint32_t*>(Qlo + r_b * QH_STR + 8 * ks + tg + 4);
    }

    float o[16][4];
#pragma unroll
    for (int nc = 0; nc < 16; nc++)
#pragma unroll
        for (int j = 0; j < 4; j++) o[nc][j] = 0.f;
    float m_a = -1e30f, m_b = -1e30f, l_a = 0.f, l_b = 0.f;

    for (int it = 0; it < N / KT; it++) {
        int buf = it & 1;
        cp_wait0();        // no-op at it=0 (already waited)
        __syncthreads();

        if (it + 1 < N / KT) {
            int m0n = (it + 1) * KT;
            int bn = buf ^ 1;
            __half2* KhiN = Khi + bn * KBUF;
            __half2* KloN = Klo + bn * KBUF;
            __half2* VN   = VhT2 + bn * VBUF;
            for (int idx = tid; idx < 64 * 16; idx += 256) {
                int p = idx >> 4, mq = (idx & 15) * 4;
                cp16(KhiN + p * KH_STR + mq, g_kh2 + (size_t)p * BN_TOK + bN0 + m0n + mq);
                cp16(KloN + p * KH_STR + mq, g_kl2 + (size_t)p * BN_TOK + bN0 + m0n + mq);
            }
            int tp0 = (bN0 + m0n) >> 1;
            for (int idx = tid; idx < HD * 8; idx += 256) {
                int k = idx >> 3, tq = (idx & 7) * 4;
                cp16(VN + k * VT2_STR + tq, g_vh2 + (size_t)k * (BN_TOK / 2) + tp0 + tq);
            }
            cp_commit();
        }

        __half2* KhiB = Khi + buf * KBUF;
        __half2* KloB = Klo + buf * KBUF;
        __half2* VB   = VhT2 + buf * VBUF;

        // ---- S = Q K^T : f16 compensated, A fragments from registers ----
        float scc[8][4] = {};
        float scl[8][4] = {};
#pragma unroll
        for (int ks = 0; ks < 8; ks++) {
            const __half2* kh0 = KhiB + (8 * ks + tg) * KH_STR + g;
            const __half2* kh1 = KhiB + (8 * ks + 4 + tg) * KH_STR + g;
            const __half2* kl0 = KloB + (8 * ks + tg) * KH_STR + g;
            const __half2* kl1 = KloB + (8 * ks + 4 + tg) * KH_STR + g;
#pragma unroll
            for (int nc = 0; nc < 8; nc++) {
                uint32_t bh[2] = { *reinterpret_cast<const uint32_t*>(kh0 + 8 * nc),
                                   *reinterpret_cast<const uint32_t*>(kh1 + 8 * nc) };
                uint32_t bl[2] = { *reinterpret_cast<const uint32_t*>(kl0 + 8 * nc),
                                   *reinterpret_cast<const uint32_t*>(kl1 + 8 * nc) };
                mma_f16(scc[nc], qh[ks], bh);
                mma_f16(scl[nc], ql[ks], bh);
                mma_f16(scl[nc], qh[ks], bl);
            }
        }
#pragma unroll
        for (int nc = 0; nc < 8; nc++)
#pragma unroll
            for (int j = 0; j < 4; j++)
                scc[nc][j] += scl[nc][j] * LO_INV;

        // ---- online softmax (log2 domain, f16x2 ex2); P in registers ----
        float lm_a = -1e30f, lm_b = -1e30f;
#pragma unroll
        for (int nc = 0; nc < 8; nc++) {
            lm_a = fmaxf(lm_a, fmaxf(scc[nc][0], scc[nc][1]));
            lm_b = fmaxf(lm_b, fmaxf(scc[nc][2], scc[nc][3]));
        }
#pragma unroll
        for (int off = 1; off <= 2; off <<= 1) {
            lm_a = fmaxf(lm_a, __shfl_xor_sync(0xffffffffu, lm_a, off));
            lm_b = fmaxf(lm_b, __shfl_xor_sync(0xffffffffu, lm_b, off));
        }
        float mn_a = fmaxf(m_a, lm_a), mn_b = fmaxf(m_b, lm_b);
        float al_a = exp2f(m_a - mn_a), al_b = exp2f(m_b - mn_b);
        m_a = mn_a; m_b = mn_b;

        uint32_t pha[8], phb[8];
        float rs_a = 0.f, rs_b = 0.f;
#pragma unroll
        for (int nc = 0; nc < 8; nc++) {
            __half2 ha = h2exp2(__floats2half2_rn(scc[nc][0] - mn_a, scc[nc][1] - mn_a));
            __half2 hb = h2exp2(__floats2half2_rn(scc[nc][2] - mn_b, scc[nc][3] - mn_b));
            pha[nc] = *reinterpret_cast<uint32_t*>(&ha);
            phb[nc] = *reinterpret_cast<uint32_t*>(&hb);
            float2 fa = __half22float2(ha);
            float2 fb = __half22float2(hb);
            rs_a += fa.x + fa.y;
            rs_b += fb.x + fb.y;
        }
#pragma unroll
        for (int off = 1; off <= 2; off <<= 1) {
            rs_a += __shfl_xor_sync(0xffffffffu, rs_a, off);
            rs_b += __shfl_xor_sync(0xffffffffu, rs_b, off);
        }
        l_a = l_a * al_a + rs_a;
        l_b = l_b * al_b + rs_b;
        // rescale only when the running max changed (x1.0 skip is bit-exact)
        if (al_a != 1.f) {
#pragma unroll
            for (int nc = 0; nc < 16; nc++) { o[nc][0] *= al_a; o[nc][1] *= al_a; }
        }
        if (al_b != 1.f) {
#pragma unroll
            for (int nc = 0; nc < 16; nc++) { o[nc][2] *= al_b; o[nc][3] *= al_b; }
        }

        // ---- O += P V ----
#pragma unroll
        for (int ks = 0; ks < 4; ks++) {
            uint32_t a[4] = { pha[2 * ks], phb[2 * ks], pha[2 * ks + 1], phb[2 * ks + 1] };
#pragma unroll
            for (int nc = 0; nc < 16; nc++) {
                const __half2* vb = VB + (8 * nc + g) * VT2_STR + 8 * ks + tg;
                uint32_t bb[2];
                bb[0] = *reinterpret_cast<const uint32_t*>(vb);
                bb[1] = *reinterpret_cast<const uint32_t*>(vb + 4);
                mma_f16(o[nc], a, bb);
            }
        }
    }

    float inv_a = 1.f / l_a, inv_b = 1.f / l_b;
    __half2* dsta = g_attno2 + (((size_t)(bN0 + n0 + r_a)) * H + h) * (HD / 2);
    __half2* dstb = g_attno2 + (((size_t)(bN0 + n0 + r_b)) * H + h) * (HD / 2);
#pragma unroll
    for (int nc = 0; nc < 16; nc++) {
        int p = 4 * nc + tg;
        dsta[p] = __floats2half2_rn(o[nc][0] * inv_a, o[nc][1] * inv_a);
        dstb[p] = __floats2half2_rn(o[nc][2] * inv_b, o[nc][3] * inv_b);
    }
}

// ---------------------------------------------------------------------------
// Kernel 7: grouped combine GEMM — single-pass f16, cp.async loads,
// f16 output scratch.
// ---------------------------------------------------------------------------
constexpr int CA_STR = 68;
constexpr int CB_STR = 136;

__global__ __launch_bounds__(256, 2) void cgemm_kernel()
{
    extern __shared__ __half2 csm[];
    __half2* A2 = csm;                  // 128*68
    __half2* B2 = A2 + TQ * CA_STR;     // 64*136
    int*   s_slot = reinterpret_cast<int*>(B2 + 64 * CB_STR);
    float* s_gate = reinterpret_cast<float*>(s_slot + TQ);

    int t = blockIdx.x;
    if (t >= g_ntiles) return;
    int n0 = blockIdx.y * 128;
    int e = g_tile_e[t], r0 = g_tile_r0[t];
    int rend = g_eoff[e + 1];
    int tid = threadIdx.x;

    if (tid < TQ) {
        int gr = r0 + tid;
        if (gr >= rend) gr = r0;
        int s = g_slots[gr];
        s_slot[tid] = s;
        s_gate[tid] = g_gates[s];
    }
    __syncthreads();

    for (int idx = tid; idx < TQ * 16; idx += 256) {
        int r = idx >> 4, pq = (idx & 15) * 4;
        cp16(A2 + r * CA_STR + pq, g_attno2 + (size_t)s_slot[r] * (HD / 2) + pq);
    }
    for (int idx = tid; idx < 64 * 32; idx += 256) {
        int p = idx >> 5, nq = (idx & 31) * 4;
        cp16(B2 + p * CB_STR + nq, g_woh2 + ((size_t)e * (HD / 2) + p) * D + n0 + nq);
    }
    cp_commit();
    cp_wait0();
    __syncthreads();

    int warp = tid >> 5, lane = tid & 31;
    int g = lane >> 2, tg = lane & 3;
    int r_a = warp * 16 + g, r_b = r_a + 8;

    float acc[16][4] = {};

#pragma unroll
    for (int ks = 0; ks < 8; ks++) {
        const __half2* a0 = A2 + r_a * CA_STR + 8 * ks + tg;
        const __half2* a1 = A2 + r_b * CA_STR + 8 * ks + tg;
        uint32_t a[4] = { *reinterpret_cast<const uint32_t*>(a0),
                          *reinterpret_cast<const uint32_t*>(a1),
                          *reinterpret_cast<const uint32_t*>(a0 + 4),
                          *reinterpret_cast<const uint32_t*>(a1 + 4) };
        const __half2* b0 = B2 + (8 * ks + tg) * CB_STR + g;
        const __half2* b1 = B2 + (8 * ks + 4 + tg) * CB_STR + g;
#pragma unroll
        for (int nc = 0; nc < 16; nc++) {
            uint32_t bb[2] = { *reinterpret_cast<const uint32_t*>(b0 + 8 * nc),
                               *reinterpret_cast<const uint32_t*>(b1 + 8 * nc) };
            mma_f16(acc[nc], a, bb);
        }
    }

    bool va = (r0 + r_a < rend), vb = (r0 + r_b < rend);
    float ga = s_gate[r_a], gb = s_gate[r_b];
    __half2* da = g_ws2 + (size_t)s_slot[r_a] * (D / 2) + (n0 >> 1);
    __half2* db = g_ws2 + (size_t)s_slot[r_b] * (D / 2) + (n0 >> 1);
#pragma unroll
    for (int nc = 0; nc < 16; nc++) {
        int p = 4 * nc + tg;
        if (va) da[p] = __floats2half2_rn(acc[nc][0] * ga, acc[nc][1] * ga);
        if (vb) db[p] = __floats2half2_rn(acc[nc][2] * gb, acc[nc][3] * gb);
    }
}

// ---------------------------------------------------------------------------
// Kernel 8: reduce 8 slot rows per token → y  (f16 in, f32 out)
// ---------------------------------------------------------------------------
__global__ __launch_bounds__(256) void reduce_kernel(float* __restrict__ y)
{
    int t = blockIdx.x;
    int p = threadIdx.x * 2;
    float4 s = make_float4(0.f, 0.f, 0.f, 0.f);
#pragma unroll
    for (int h = 0; h < H; h++) {
        const __half2* w = g_ws2 + ((size_t)(t * H + h)) * (D / 2) + p;
        float2 a = __half22float2(w[0]);
        float2 b2 = __half22float2(w[1]);
        s.x += a.x; s.y += a.y; s.z += b2.x; s.w += b2.y;
    }
    *reinterpret_cast<float4*>(y + (size_t)t * D + p * 2) = s;
}

// ---------------------------------------------------------------------------
// Kernel 9: finalize aux loss
// ---------------------------------------------------------------------------
__global__ void aux_final_kernel(float* __restrict__ out) {
    if (threadIdx.x == 0) {
        const float inv_bn = 1.0f / (float)BN_TOK;
        float sw = 0.f;
        for (int e = 0; e < E; e++)
            sw += (g_aux[e] * inv_bn) * (g_aux[E + e] * inv_bn);
        float aux = 0.1f * (float)E * sw + 0.001f * (g_aux[2 * E] * inv_bn);
        out[(size_t)BN_TOK * D] = aux;
    }
}

// ---------------------------------------------------------------------------
// Launch
// ---------------------------------------------------------------------------
extern "C" void kernel_launch(void* const* d_in, const int* in_sizes, int n_in,
                              void* d_out, int out_size)
{
    const float* x    = (const float*)d_in[0];
    const int* task_bh = (const int*)d_in[1];
    const float* Wg   = (const float*)d_in[2];
    const float* Wq   = (const float*)d_in[3];
    const float* Wo   = (const float*)d_in[4];
    const float* Wkv  = (const float*)d_in[5];
    const float* bkv  = (const float*)d_in[6];
    float* out = (float*)d_out;

    const int attn_smem = (2 * QT * QH_STR + 4 * KBUF + 2 * VBUF) * 4;
    const int qg_smem = (4 * QABUF + 4 * QBBUF) * 4 + 2 * TQ * 4;
    const int cg_smem = (TQ * CA_STR + 64 * CB_STR) * 4 + 2 * TQ * 4;
    const int gate_smem = D * E * 4;
    cudaFuncSetAttribute(attn_kernel,   cudaFuncAttributeMaxDynamicSharedMemorySize, attn_smem);
    cudaFuncSetAttribute(qgemm_kernel,  cudaFuncAttributeMaxDynamicSharedMemorySize, qg_smem);
    cudaFuncSetAttribute(kvmma_kernel,  cudaFuncAttributeMaxDynamicSharedMemorySize, qg_smem);
    cudaFuncSetAttribute(cgemm_kernel,  cudaFuncAttributeMaxDynamicSharedMemorySize, cg_smem);
    cudaFuncSetAttribute(gating_kernel, cudaFuncAttributeMaxDynamicSharedMemorySize, gate_smem);

    init_aux_kernel<<<1, 64>>>();
    xsplit_kernel<<<BN_TOK, 256>>>(x);
    wqsplit_kernel<<<dim3(D / 2, E), 128>>>(Wq);
    wosplit_kernel<<<dim3(HD / 2, E), 256>>>(Wo);
    wkvsplit_kernel<<<D / 2, 256>>>(Wkv);
    gating_kernel<<<BN_TOK / 8, 256, gate_smem>>>(x, task_bh, Wg);
    scan_kernel<<<1, 32>>>();
    scatter_kernel<<<NSLOT / 256, 256>>>();
    kvmma_kernel<<<dim3(BN_TOK / TQ, 2), 512, qg_smem>>>(bkv);
    qgemm_kernel<<<NT_MAX, 512, qg_smem>>>();
    attn_kernel<<<dim3(N / QT, H, B), 256, attn_smem>>>();
    cgemm_kernel<<<dim3(NT_MAX, 8), 256, cg_smem>>>();
    reduce_kernel<<<BN_TOK, 256>>>(out);
    aux_final_kernel<<<1, 32>>>(out);
}